// round 2
// baseline (speedup 1.0000x reference)
#include <cuda_runtime.h>
#include <math.h>

#define NN 50000
#define BB 8
#define FF 32
#define EE 800000
#define NB (NN * BB)          // 400000 rows
#define ROWF (BB * FF)        // 256 floats per node row
#define ROWV (ROWF / 4)       // 64 float4 per node row

// ---------------- scratch (static device globals; no allocation) -------------
__device__ float4 g_bufA[NB * 8];     // 51.2 MB  (dinv-scaled linear outputs)
__device__ float4 g_bufB[NB * 8];     // 51.2 MB  (post-aggregation activations)
__device__ float  g_h3[NN * BB];      // 1.6 MB   (layer-3 linear outputs, [n][b])
__device__ int    g_degi[NN];
__device__ float  g_dinv[NN];
__device__ int    g_rowptr[NN + 1];
__device__ int    g_cursor[NN];
__device__ int    g_csrc[EE];

// ---------------- CSR build --------------------------------------------------
__global__ __launch_bounds__(256) void init_kernel(float* out) {
    int i = blockIdx.x * 256 + threadIdx.x;
    if (i < NN) g_degi[i] = 1;                 // self-loop
    if (blockIdx.x == 0 && threadIdx.x < BB) out[threadIdx.x] = 0.0f;
}

__global__ __launch_bounds__(256) void count_kernel(const int* __restrict__ ei) {
    int e = blockIdx.x * 256 + threadIdx.x;
    if (e < EE) atomicAdd(&g_degi[ei[EE + e]], 1);
}

// single-block hierarchical exclusive scan over (deg-1); also computes dinv
__global__ __launch_bounds__(1024) void scan_kernel() {
    __shared__ int wsum[33];
    int t = threadIdx.x, lane = t & 31, w = t >> 5;
    int carry = 0;
    const unsigned FULL = 0xffffffffu;
    for (int chunk = 0; chunk < 49; ++chunk) {
        int i = chunk * 1024 + t;
        int v = 0;
        if (i < NN) {
            int d = g_degi[i];
            v = d - 1;
            g_dinv[i] = rsqrtf((float)d);
        }
        int incl = v;
        #pragma unroll
        for (int o = 1; o < 32; o <<= 1) {
            int tt = __shfl_up_sync(FULL, incl, o);
            if (lane >= o) incl += tt;
        }
        if (lane == 31) wsum[w] = incl;
        __syncthreads();
        if (w == 0) {
            int s = wsum[lane];
            int si = s;
            #pragma unroll
            for (int o = 1; o < 32; o <<= 1) {
                int tt = __shfl_up_sync(FULL, si, o);
                if (lane >= o) si += tt;
            }
            wsum[lane] = si - s;               // exclusive warp offsets
            if (lane == 31) wsum[32] = si;     // chunk total
        }
        __syncthreads();
        int excl = carry + wsum[w] + (incl - v);
        if (i < NN) { g_rowptr[i] = excl; g_cursor[i] = excl; }
        carry += wsum[32];
        __syncthreads();
    }
    if (t == 0) g_rowptr[NN] = carry;
}

__global__ __launch_bounds__(256) void fill_kernel(const int* __restrict__ ei) {
    int e = blockIdx.x * 256 + threadIdx.x;
    if (e < EE) {
        int d = ei[EE + e];
        int pos = atomicAdd(&g_cursor[d], 1);
        g_csrc[pos] = ei[e];
    }
}

// ---------------- dense F x F matmul (warp per row, shuffle broadcast) -------
// out = g_bufA : row nb -> dinv[n] * (in_row @ W)
__global__ __launch_bounds__(256) void mm_kernel(const float* __restrict__ x,
                                                 const float* __restrict__ W,
                                                 int from_x) {
    const unsigned FULL = 0xffffffffu;
    int t = threadIdx.x, lane = t & 31, w = t >> 5;
    float wc[32];
    #pragma unroll
    for (int k = 0; k < 32; ++k) wc[k] = W[k * 32 + lane];

    float* outF = (float*)g_bufA;
    const float* inF = (const float*)g_bufB;

    int nwarps = gridDim.x * 8;
    for (int row = blockIdx.x * 8 + w; row < NB; row += nwarps) {
        int n = row >> 3, b = row & 7;
        float xv;
        if (from_x) xv = x[((size_t)b * NN + n) * 32 + lane];
        else        xv = inF[(size_t)row * 32 + lane];
        float a0 = 0.f, a1 = 0.f;
        #pragma unroll
        for (int k = 0; k < 32; k += 2) {
            a0 = fmaf(__shfl_sync(FULL, xv, k),     wc[k],     a0);
            a1 = fmaf(__shfl_sync(FULL, xv, k + 1), wc[k + 1], a1);
        }
        outF[(size_t)row * 32 + lane] = (a0 + a1) * g_dinv[n];
    }
}

// ---------------- sparse aggregation (gather, no atomics) --------------------
// reads g_bufA (dinv-prescaled), writes g_bufB = relu(dinv[n]*(self+sum)+bias)
__global__ __launch_bounds__(256) void gather_kernel(const float* __restrict__ bias) {
    int t = threadIdx.x;
    int n = blockIdx.x * 4 + (t >> 6);
    int c = t & 63;
    const float4* gin = g_bufA;
    float4 acc = gin[n * ROWV + c];                         // self term
    int j = g_rowptr[n], jend = g_rowptr[n + 1];

    if (j + 4 <= jend) {
        // prefetch first index quad
        int s0 = g_csrc[j], s1 = g_csrc[j + 1], s2 = g_csrc[j + 2], s3 = g_csrc[j + 3];
        j += 4;
        while (j + 4 <= jend) {
            // issue value loads for current quad
            float4 v0 = gin[s0 * ROWV + c];
            float4 v1 = gin[s1 * ROWV + c];
            float4 v2 = gin[s2 * ROWV + c];
            float4 v3 = gin[s3 * ROWV + c];
            // prefetch next index quad while values are in flight
            s0 = g_csrc[j]; s1 = g_csrc[j + 1]; s2 = g_csrc[j + 2]; s3 = g_csrc[j + 3];
            j += 4;
            acc.x += v0.x + v1.x + v2.x + v3.x;
            acc.y += v0.y + v1.y + v2.y + v3.y;
            acc.z += v0.z + v1.z + v2.z + v3.z;
            acc.w += v0.w + v1.w + v2.w + v3.w;
        }
        float4 v0 = gin[s0 * ROWV + c];
        float4 v1 = gin[s1 * ROWV + c];
        float4 v2 = gin[s2 * ROWV + c];
        float4 v3 = gin[s3 * ROWV + c];
        acc.x += v0.x + v1.x + v2.x + v3.x;
        acc.y += v0.y + v1.y + v2.y + v3.y;
        acc.z += v0.z + v1.z + v2.z + v3.z;
        acc.w += v0.w + v1.w + v2.w + v3.w;
    }
    for (; j < jend; ++j) {
        float4 v = gin[g_csrc[j] * ROWV + c];
        acc.x += v.x; acc.y += v.y; acc.z += v.z; acc.w += v.w;
    }
    float dn = g_dinv[n];
    int fb = (c & 7) * 4;                                   // feature base within 0..31
    float4 r;
    r.x = fmaxf(fmaf(dn, acc.x, bias[fb + 0]), 0.f);
    r.y = fmaxf(fmaf(dn, acc.y, bias[fb + 1]), 0.f);
    r.z = fmaxf(fmaf(dn, acc.z, bias[fb + 2]), 0.f);
    r.w = fmaxf(fmaf(dn, acc.w, bias[fb + 3]), 0.f);
    g_bufB[n * ROWV + c] = r;
}

// ---------------- layer 3: F -> 1 (warp per row, reduce) ---------------------
__global__ __launch_bounds__(256) void mm3_kernel(const float* __restrict__ W3) {
    const unsigned FULL = 0xffffffffu;
    int t = threadIdx.x, lane = t & 31, w = t >> 5;
    float w3 = W3[lane];
    const float* inF = (const float*)g_bufB;
    int nwarps = gridDim.x * 8;
    for (int row = blockIdx.x * 8 + w; row < NB; row += nwarps) {
        float v = inF[(size_t)row * 32 + lane] * w3;
        #pragma unroll
        for (int o = 16; o; o >>= 1) v += __shfl_xor_sync(FULL, v, o);
        if (lane == 0) g_h3[row] = v * g_dinv[row >> 3];
    }
}

// ---------------- final: aggregate F=1, sigmoid, per-batch sum ---------------
__global__ __launch_bounds__(256) void final_kernel(const float* __restrict__ b3,
                                                    float* __restrict__ out) {
    int t = threadIdx.x;
    int node = blockIdx.x * 32 + (t >> 3);
    int b = t & 7;
    float p = 0.f;
    if (node < NN) {
        float acc = g_h3[node * 8 + b];
        int jb = g_rowptr[node], je = g_rowptr[node + 1];
        for (int j = jb; j < je; ++j) acc += g_h3[g_csrc[j] * 8 + b];
        float z = fmaf(g_dinv[node], acc, b3[0]);
        p = 1.f / (1.f + expf(-z));
    }
    __shared__ float red[256];
    red[t] = p;
    __syncthreads();
    #pragma unroll
    for (int off = 128; off >= 8; off >>= 1) {
        if (t < off) red[t] += red[t + off];
        __syncthreads();
    }
    if (t < 8) atomicAdd(&out[t], red[t]);
}

// ---------------- launch -----------------------------------------------------
extern "C" void kernel_launch(void* const* d_in, const int* in_sizes, int n_in,
                              void* d_out, int out_size) {
    const float* x  = (const float*)d_in[0];
    const float* W1 = (const float*)d_in[1];
    const float* b1 = (const float*)d_in[2];
    const float* W2 = (const float*)d_in[3];
    const float* b2 = (const float*)d_in[4];
    const float* W3 = (const float*)d_in[5];
    const float* b3 = (const float*)d_in[6];
    const int*   ei = (const int*)d_in[7];
    float* out = (float*)d_out;

    init_kernel<<<(NN + 255) / 256, 256>>>(out);
    count_kernel<<<EE / 256, 256>>>(ei);
    scan_kernel<<<1, 1024>>>();
    fill_kernel<<<EE / 256, 256>>>(ei);

    mm_kernel<<<1184, 256>>>(x, W1, 1);       // x @ W1 (layout transform, dinv-scaled)
    gather_kernel<<<NN / 4, 256>>>(b1);       // relu aggregate -> bufB
    mm_kernel<<<1184, 256>>>(x, W2, 0);       // bufB @ W2 -> bufA
    gather_kernel<<<NN / 4, 256>>>(b2);       // relu aggregate -> bufB
    mm3_kernel<<<1184, 256>>>(W3);            // bufB @ W3 -> g_h3
    final_kernel<<<(NN + 31) / 32, 256>>>(b3, out);
}

// round 4
// speedup vs baseline: 1.5158x; 1.5158x over previous
#include <cuda_runtime.h>
#include <cuda_fp16.h>
#include <math.h>

#define NN 50000
#define BB 8
#define FF 32
#define EE 800000
#define NB (NN * BB)          // 400000 (n,b) rows
#define FULLM 0xffffffffu

// node row = 256 halves = 512 B = 32 float4, layout [n][b][f]
__device__ float4 g_bufA16[NN * 32];   // 25.6 MB  (dinv-prescaled linear outs, fp16)
__device__ float4 g_bufB16[NN * 32];   // 25.6 MB  (post-aggregation relu acts, fp16)
__device__ float  g_h3[NN * BB];       // 1.6 MB   (layer-3 linear outs, [n][b])
__device__ int    g_degi[NN];
__device__ float  g_dinv[NN];
__device__ int    g_rowstart[NN];
__device__ int    g_rowend[NN];
__device__ int    g_cursor[NN];
__device__ int    g_csrc[EE];
__device__ int    g_total;

// ---------------- CSR build --------------------------------------------------
__global__ __launch_bounds__(256) void init_kernel(float* out) {
    int i = blockIdx.x * 256 + threadIdx.x;
    if (i < NN) g_degi[i] = 1;                 // self-loop
    if (blockIdx.x == 0 && threadIdx.x < BB) out[threadIdx.x] = 0.0f;
    if (blockIdx.x == 0 && threadIdx.x == 0) g_total = 0;
}

__global__ __launch_bounds__(256) void count_kernel(const int* __restrict__ ei) {
    int e = blockIdx.x * 256 + threadIdx.x;
    if (e < EE) atomicAdd(&g_degi[ei[EE + e]], 1);
}

// parallel segment assignment (order-free CSR): warp-aggregated atomic
__global__ __launch_bounds__(256) void seg_kernel() {
    int i = blockIdx.x * 256 + threadIdx.x;
    int lane = threadIdx.x & 31;
    int d = 1, m = 0;
    if (i < NN) { d = g_degi[i]; m = d - 1; }
    int incl = m;
    #pragma unroll
    for (int o = 1; o < 32; o <<= 1) {
        int v = __shfl_up_sync(FULLM, incl, o);
        if (lane >= o) incl += v;
    }
    int base = 0;
    if (lane == 31) base = atomicAdd(&g_total, incl);
    base = __shfl_sync(FULLM, base, 31);
    if (i < NN) {
        int start = base + incl - m;
        g_rowstart[i] = start;
        g_rowend[i]   = start + m;
        g_cursor[i]   = start;
        g_dinv[i]     = rsqrtf((float)d);
    }
}

__global__ __launch_bounds__(256) void fill_kernel(const int* __restrict__ ei) {
    int e = blockIdx.x * 256 + threadIdx.x;
    if (e < EE) {
        int d = ei[EE + e];
        int pos = atomicAdd(&g_cursor[d], 1);
        g_csrc[pos] = ei[e];
    }
}

// ---------------- dense F x F matmul (warp per row, shuffle broadcast) -------
// writes g_bufA16 : row (n,b) -> half( dinv[n] * (in_row @ W) )
__global__ __launch_bounds__(256) void mm_kernel(const float* __restrict__ x,
                                                 const float* __restrict__ W,
                                                 int from_x) {
    int t = threadIdx.x, lane = t & 31, w = t >> 5;
    float wc[32];
    #pragma unroll
    for (int k = 0; k < 32; ++k) wc[k] = W[k * 32 + lane];

    __half* outH = (__half*)g_bufA16;
    const __half* inH = (const __half*)g_bufB16;

    int nwarps = gridDim.x * 8;
    for (int row = blockIdx.x * 8 + w; row < NB; row += nwarps) {
        int n = row >> 3;
        float xv;
        if (from_x) xv = x[((size_t)(row & 7) * NN + n) * 32 + lane];
        else        xv = __half2float(inH[(size_t)row * 32 + lane]);
        float a0 = 0.f, a1 = 0.f;
        #pragma unroll
        for (int k = 0; k < 32; k += 2) {
            a0 = fmaf(__shfl_sync(FULLM, xv, k),     wc[k],     a0);
            a1 = fmaf(__shfl_sync(FULLM, xv, k + 1), wc[k + 1], a1);
        }
        outH[(size_t)row * 32 + lane] = __float2half_rn((a0 + a1) * g_dinv[n]);
    }
}

// ---------------- gather helpers ---------------------------------------------
__device__ __forceinline__ void acc8(float (&acc)[8], float4 v) {
    const __half2* p = (const __half2*)&v;
    #pragma unroll
    for (int i = 0; i < 4; ++i) {
        float2 f = __half22float2(p[i]);
        acc[2 * i] += f.x; acc[2 * i + 1] += f.y;
    }
}

// common gather body: acc = self + sum_{neighbors}, all fp16 rows unpacked to f32
__device__ __forceinline__ void gather_body(float (&acc)[8], int n, int c) {
    const float4* __restrict__ gin = g_bufA16;
    const int* __restrict__ csrc = g_csrc;
    float4 self = gin[n * 32 + c];
    #pragma unroll
    for (int i = 0; i < 8; ++i) acc[i] = 0.f;
    acc8(acc, self);
    int j = g_rowstart[n], jend = g_rowend[n];
    if (j + 4 <= jend) {
        int s0 = __ldg(csrc + j), s1 = __ldg(csrc + j + 1);
        int s2 = __ldg(csrc + j + 2), s3 = __ldg(csrc + j + 3);
        j += 4;
        while (j + 4 <= jend) {
            float4 v0 = gin[s0 * 32 + c];
            float4 v1 = gin[s1 * 32 + c];
            float4 v2 = gin[s2 * 32 + c];
            float4 v3 = gin[s3 * 32 + c];
            s0 = __ldg(csrc + j);     s1 = __ldg(csrc + j + 1);
            s2 = __ldg(csrc + j + 2); s3 = __ldg(csrc + j + 3);
            j += 4;
            acc8(acc, v0); acc8(acc, v1); acc8(acc, v2); acc8(acc, v3);
        }
        float4 v0 = gin[s0 * 32 + c];
        float4 v1 = gin[s1 * 32 + c];
        float4 v2 = gin[s2 * 32 + c];
        float4 v3 = gin[s3 * 32 + c];
        acc8(acc, v0); acc8(acc, v1); acc8(acc, v2); acc8(acc, v3);
    }
    for (; j < jend; ++j) acc8(acc, gin[__ldg(csrc + j) * 32 + c]);
}

// gather + bias + relu -> bufB16 (fp16)
__global__ __launch_bounds__(256) void gather1_kernel(const float* __restrict__ bias) {
    int t = threadIdx.x;
    int n = blockIdx.x * 8 + (t >> 5);
    int c = t & 31;
    float acc[8];
    gather_body(acc, n, c);
    float dn = g_dinv[n];
    int f0 = (c & 3) * 8;
    __half2 r[4];
    #pragma unroll
    for (int i = 0; i < 4; ++i) {
        float lo = fmaxf(fmaf(dn, acc[2 * i],     bias[f0 + 2 * i]),     0.f);
        float hi = fmaxf(fmaf(dn, acc[2 * i + 1], bias[f0 + 2 * i + 1]), 0.f);
        r[i] = __floats2half2_rn(lo, hi);
    }
    g_bufB16[n * 32 + c] = *(float4*)r;
}

// gather + bias + relu, fused layer-3 linear (dot with W3) -> g_h3
__global__ __launch_bounds__(256) void gather2_kernel(const float* __restrict__ bias,
                                                      const float* __restrict__ W3) {
    int t = threadIdx.x;
    int n = blockIdx.x * 8 + (t >> 5);
    int c = t & 31;
    float acc[8];
    gather_body(acc, n, c);
    float dn = g_dinv[n];
    int f0 = (c & 3) * 8;
    float s = 0.f;
    #pragma unroll
    for (int i = 0; i < 8; ++i) {
        float h = fmaxf(fmaf(dn, acc[i], bias[f0 + i]), 0.f);
        s = fmaf(h, W3[f0 + i], s);
    }
    s += __shfl_xor_sync(FULLM, s, 1);
    s += __shfl_xor_sync(FULLM, s, 2);
    if ((c & 3) == 0) g_h3[n * 8 + (c >> 2)] = dn * s;
}

// ---------------- final: aggregate F=1, sigmoid, per-batch sum ---------------
__global__ __launch_bounds__(256) void final_kernel(const float* __restrict__ b3,
                                                    float* __restrict__ out) {
    int t = threadIdx.x;
    int node = blockIdx.x * 32 + (t >> 3);
    int b = t & 7;
    float p = 0.f;
    if (node < NN) {
        float acc = g_h3[node * 8 + b];
        int jb = g_rowstart[node], je = g_rowend[node];
        for (int j = jb; j < je; ++j) acc += g_h3[g_csrc[j] * 8 + b];
        float z = fmaf(g_dinv[node], acc, b3[0]);
        p = 1.f / (1.f + expf(-z));
    }
    __shared__ float red[256];
    red[t] = p;
    __syncthreads();
    #pragma unroll
    for (int off = 128; off >= 8; off >>= 1) {
        if (t < off) red[t] += red[t + off];
        __syncthreads();
    }
    if (t < 8) atomicAdd(&out[t], red[t]);
}

// ---------------- launch -----------------------------------------------------
extern "C" void kernel_launch(void* const* d_in, const int* in_sizes, int n_in,
                              void* d_out, int out_size) {
    const float* x  = (const float*)d_in[0];
    const float* W1 = (const float*)d_in[1];
    const float* b1 = (const float*)d_in[2];
    const float* W2 = (const float*)d_in[3];
    const float* b2 = (const float*)d_in[4];
    const float* W3 = (const float*)d_in[5];
    const float* b3 = (const float*)d_in[6];
    const int*   ei = (const int*)d_in[7];
    float* out = (float*)d_out;

    init_kernel<<<(NN + 255) / 256, 256>>>(out);
    count_kernel<<<EE / 256, 256>>>(ei);
    seg_kernel<<<(NN + 255) / 256, 256>>>();
    fill_kernel<<<EE / 256, 256>>>(ei);

    mm_kernel<<<1184, 256>>>(x, W1, 1);       // x @ W1 (dinv-prescaled) -> bufA16
    gather1_kernel<<<NN / 8, 256>>>(b1);      // aggregate + relu -> bufB16
    mm_kernel<<<1184, 256>>>(x, W2, 0);       // bufB16 @ W2 -> bufA16
    gather2_kernel<<<NN / 8, 256>>>(b2, W3);  // aggregate + relu + @W3 -> g_h3
    final_kernel<<<(NN + 31) / 32, 256>>>(b3, out);
}

// round 6
// speedup vs baseline: 1.5248x; 1.0059x over previous
#include <cuda_runtime.h>
#include <cuda_fp16.h>
#include <cuda_fp8.h>
#include <math.h>

#define NN 50000
#define BB 8
#define FF 32
#define EE 800000
#define NB (NN * BB)          // 400000 (n,b) rows
#define FULLM 0xffffffffu

// node row = 256 fp8 = 256 B = 32 uint2, layout [n][b][f]
__device__ uint2  g_bufA8[NN * 32];    // 12.8 MB  (dinv-prescaled linear outs, fp8 e4m3)
__device__ uint2  g_bufB8[NN * 32];    // 12.8 MB  (post-aggregation relu acts, fp8 e4m3)
__device__ float  g_h3[NN * BB];       // 1.6 MB   (layer-3 linear outs, [n][b])
__device__ int    g_degi[NN];
__device__ float  g_dinv[NN];
__device__ int    g_rowstart[NN];
__device__ int    g_rowend[NN];
__device__ int    g_cursor[NN];
__device__ int    g_csrc[EE];
__device__ int    g_total;

// ---------------- CSR build --------------------------------------------------
__global__ __launch_bounds__(256) void init_kernel(float* out) {
    int i = blockIdx.x * 256 + threadIdx.x;
    if (i < NN) g_degi[i] = 1;                 // self-loop
    if (blockIdx.x == 0 && threadIdx.x < BB) out[threadIdx.x] = 0.0f;
    if (blockIdx.x == 0 && threadIdx.x == 0) g_total = 0;
}

__global__ __launch_bounds__(256) void count_kernel(const int* __restrict__ ei) {
    int e4 = blockIdx.x * 256 + threadIdx.x;
    if (e4 < EE / 4) {
        int4 d = ((const int4*)(ei + EE))[e4];
        atomicAdd(&g_degi[d.x], 1);
        atomicAdd(&g_degi[d.y], 1);
        atomicAdd(&g_degi[d.z], 1);
        atomicAdd(&g_degi[d.w], 1);
    }
}

// parallel segment assignment (order-free CSR): warp-aggregated atomic
__global__ __launch_bounds__(256) void seg_kernel() {
    int i = blockIdx.x * 256 + threadIdx.x;
    int lane = threadIdx.x & 31;
    int d = 1, m = 0;
    if (i < NN) { d = g_degi[i]; m = d - 1; }
    int incl = m;
    #pragma unroll
    for (int o = 1; o < 32; o <<= 1) {
        int v = __shfl_up_sync(FULLM, incl, o);
        if (lane >= o) incl += v;
    }
    int base = 0;
    if (lane == 31) base = atomicAdd(&g_total, incl);
    base = __shfl_sync(FULLM, base, 31);
    if (i < NN) {
        int start = base + incl - m;
        g_rowstart[i] = start;
        g_rowend[i]   = start + m;
        g_cursor[i]   = start;
        g_dinv[i]     = rsqrtf((float)d);
    }
}

__global__ __launch_bounds__(256) void fill_kernel(const int* __restrict__ ei) {
    int e4 = blockIdx.x * 256 + threadIdx.x;
    if (e4 < EE / 4) {
        int4 s = ((const int4*)ei)[e4];
        int4 d = ((const int4*)(ei + EE))[e4];
        g_csrc[atomicAdd(&g_cursor[d.x], 1)] = s.x;
        g_csrc[atomicAdd(&g_cursor[d.y], 1)] = s.y;
        g_csrc[atomicAdd(&g_cursor[d.z], 1)] = s.z;
        g_csrc[atomicAdd(&g_cursor[d.w], 1)] = s.w;
    }
}

// ---------------- fp8 helpers ------------------------------------------------
__device__ __forceinline__ unsigned char f2fp8(float v) {
    return (unsigned char)__nv_cvt_float_to_fp8(v, __NV_SATFINITE, __NV_E4M3);
}
__device__ __forceinline__ float fp82f(unsigned char b) {
    return __half2float(__half(__nv_cvt_fp8_to_halfraw((__nv_fp8_storage_t)b, __NV_E4M3)));
}

// ---------------- dense F x F matmul (warp per row, shuffle broadcast) -------
// writes g_bufA8 : row (n,b) -> fp8( dinv[n] * (in_row @ W) )
__global__ __launch_bounds__(256) void mm_kernel(const float* __restrict__ x,
                                                 const float* __restrict__ W,
                                                 int from_x) {
    int t = threadIdx.x, lane = t & 31, w = t >> 5;
    float wc[32];
    #pragma unroll
    for (int k = 0; k < 32; ++k) wc[k] = W[k * 32 + lane];

    unsigned char* outB = (unsigned char*)g_bufA8;
    const unsigned char* inB = (const unsigned char*)g_bufB8;

    int nwarps = gridDim.x * 8;
    for (int row = blockIdx.x * 8 + w; row < NB; row += nwarps) {
        int n = row >> 3;
        float xv;
        if (from_x) xv = x[((size_t)(row & 7) * NN + n) * 32 + lane];
        else        xv = fp82f(inB[(size_t)row * 32 + lane]);
        float a0 = 0.f, a1 = 0.f;
        #pragma unroll
        for (int k = 0; k < 32; k += 2) {
            a0 = fmaf(__shfl_sync(FULLM, xv, k),     wc[k],     a0);
            a1 = fmaf(__shfl_sync(FULLM, xv, k + 1), wc[k + 1], a1);
        }
        outB[(size_t)row * 32 + lane] = f2fp8((a0 + a1) * g_dinv[n]);
    }
}

// ---------------- gather helpers ---------------------------------------------
__device__ __forceinline__ void acc8v(float (&acc)[8], uint2 v) {
    const __nv_fp8x2_storage_t* p = (const __nv_fp8x2_storage_t*)&v;
    #pragma unroll
    for (int i = 0; i < 4; ++i) {
        __half2 h = __half2(__nv_cvt_fp8x2_to_halfraw2(p[i], __NV_E4M3));
        float2 f = __half22float2(h);
        acc[2 * i] += f.x; acc[2 * i + 1] += f.y;
    }
}

// common gather body: acc = self + sum_{neighbors}, fp8 rows unpacked to f32
__device__ __forceinline__ void gather_body(float (&acc)[8], int n, int c) {
    const uint2* __restrict__ gin = g_bufA8;
    const int* __restrict__ csrc = g_csrc;
    #pragma unroll
    for (int i = 0; i < 8; ++i) acc[i] = 0.f;
    acc8v(acc, gin[n * 32 + c]);                            // self term
    int j = g_rowstart[n], jend = g_rowend[n];
    if (j + 4 <= jend) {
        int s0 = __ldg(csrc + j), s1 = __ldg(csrc + j + 1);
        int s2 = __ldg(csrc + j + 2), s3 = __ldg(csrc + j + 3);
        j += 4;
        while (j + 4 <= jend) {
            uint2 v0 = gin[s0 * 32 + c];
            uint2 v1 = gin[s1 * 32 + c];
            uint2 v2 = gin[s2 * 32 + c];
            uint2 v3 = gin[s3 * 32 + c];
            s0 = __ldg(csrc + j);     s1 = __ldg(csrc + j + 1);
            s2 = __ldg(csrc + j + 2); s3 = __ldg(csrc + j + 3);
            j += 4;
            acc8v(acc, v0); acc8v(acc, v1); acc8v(acc, v2); acc8v(acc, v3);
        }
        uint2 v0 = gin[s0 * 32 + c];
        uint2 v1 = gin[s1 * 32 + c];
        uint2 v2 = gin[s2 * 32 + c];
        uint2 v3 = gin[s3 * 32 + c];
        acc8v(acc, v0); acc8v(acc, v1); acc8v(acc, v2); acc8v(acc, v3);
    }
    for (; j < jend; ++j) acc8v(acc, gin[__ldg(csrc + j) * 32 + c]);
}

// gather + bias + relu -> bufB8 (fp8)
__global__ __launch_bounds__(256) void gather1_kernel(const float* __restrict__ bias) {
    int t = threadIdx.x;
    int n = blockIdx.x * 8 + (t >> 5);
    int c = t & 31;
    float acc[8];
    gather_body(acc, n, c);
    float dn = g_dinv[n];
    int f0 = (c & 3) * 8;
    union { unsigned short h[4]; uint2 v; } r;
    #pragma unroll
    for (int i = 0; i < 4; ++i) {
        float lo = fmaxf(fmaf(dn, acc[2 * i],     bias[f0 + 2 * i]),     0.f);
        float hi = fmaxf(fmaf(dn, acc[2 * i + 1], bias[f0 + 2 * i + 1]), 0.f);
        r.h[i] = (unsigned short)__nv_cvt_float2_to_fp8x2(make_float2(lo, hi),
                                                          __NV_SATFINITE, __NV_E4M3);
    }
    g_bufB8[n * 32 + c] = r.v;
}

// gather + bias + relu, fused layer-3 linear (dot with W3) -> g_h3
__global__ __launch_bounds__(256) void gather2_kernel(const float* __restrict__ bias,
                                                      const float* __restrict__ W3) {
    int t = threadIdx.x;
    int n = blockIdx.x * 8 + (t >> 5);
    int c = t & 31;
    float acc[8];
    gather_body(acc, n, c);
    float dn = g_dinv[n];
    int f0 = (c & 3) * 8;
    float s = 0.f;
    #pragma unroll
    for (int i = 0; i < 8; ++i) {
        float h = fmaxf(fmaf(dn, acc[i], bias[f0 + i]), 0.f);
        s = fmaf(h, W3[f0 + i], s);
    }
    s += __shfl_xor_sync(FULLM, s, 1);
    s += __shfl_xor_sync(FULLM, s, 2);
    if ((c & 3) == 0) g_h3[n * 8 + (c >> 2)] = dn * s;
}

// ---------------- final: aggregate F=1, sigmoid, per-batch sum ---------------
__global__ __launch_bounds__(256) void final_kernel(const float* __restrict__ b3,
                                                    float* __restrict__ out) {
    int t = threadIdx.x;
    int node = blockIdx.x * 32 + (t >> 3);
    int b = t & 7;
    float p = 0.f;
    if (node < NN) {
        float acc = g_h3[node * 8 + b];
        int jb = g_rowstart[node], je = g_rowend[node];
        for (int j = jb; j < je; ++j) acc += g_h3[g_csrc[j] * 8 + b];
        float z = fmaf(g_dinv[node], acc, b3[0]);
        p = 1.f / (1.f + expf(-z));
    }
    __shared__ float red[256];
    red[t] = p;
    __syncthreads();
    #pragma unroll
    for (int off = 128; off >= 8; off >>= 1) {
        if (t < off) red[t] += red[t + off];
        __syncthreads();
    }
    if (t < 8) atomicAdd(&out[t], red[t]);
}

// ---------------- launch -----------------------------------------------------
extern "C" void kernel_launch(void* const* d_in, const int* in_sizes, int n_in,
                              void* d_out, int out_size) {
    const float* x  = (const float*)d_in[0];
    const float* W1 = (const float*)d_in[1];
    const float* b1 = (const float*)d_in[2];
    const float* W2 = (const float*)d_in[3];
    const float* b2 = (const float*)d_in[4];
    const float* W3 = (const float*)d_in[5];
    const float* b3 = (const float*)d_in[6];
    const int*   ei = (const int*)d_in[7];
    float* out = (float*)d_out;

    init_kernel<<<(NN + 255) / 256, 256>>>(out);
    count_kernel<<<(EE / 4 + 255) / 256, 256>>>(ei);
    seg_kernel<<<(NN + 255) / 256, 256>>>();
    fill_kernel<<<(EE / 4 + 255) / 256, 256>>>(ei);

    mm_kernel<<<1184, 256>>>(x, W1, 1);       // x @ W1 (dinv-prescaled) -> bufA8
    gather1_kernel<<<NN / 8, 256>>>(b1);      // aggregate + relu -> bufB8
    mm_kernel<<<1184, 256>>>(x, W2, 0);       // bufB8 @ W2 -> bufA8
    gather2_kernel<<<NN / 8, 256>>>(b2, W3);  // aggregate + relu + @W3 -> g_h3
    final_kernel<<<(NN + 31) / 32, 256>>>(b3, out);
}

// round 7
// speedup vs baseline: 1.7032x; 1.1170x over previous
#include <cuda_runtime.h>
#include <cuda_fp16.h>
#include <cuda_fp8.h>
#include <math.h>

#define NN 50000
#define BB 8
#define FF 32
#define EE 800000
#define NB (NN * BB)          // 400000 (n,b) rows
#define FULLM 0xffffffffu

// node row = 256 fp8 = 256 B = 16 uint4, layout [n][b][f]
__device__ uint4  g_bufA8[NN * 16];    // 12.8 MB  (dinv-prescaled linear outs, fp8 e4m3)
__device__ uint4  g_bufB8[NN * 16];    // 12.8 MB  (post-aggregation relu acts, fp8 e4m3)
__device__ float  g_h3[NN * BB];       // 1.6 MB   (layer-3 linear outs, [n][b])
__device__ int    g_degi[NN];          // static zero-init; reset to 0 by seg each call
__device__ float  g_dinv[NN];
__device__ int    g_rowstart[NN];
__device__ int    g_rowend[NN];
__device__ int    g_cursor[NN];
__device__ int    g_csrc[EE];
__device__ int    g_total;             // static zero-init; reset to 0 by count each call

// ---------------- CSR build --------------------------------------------------
// counts edge-degree only (self-loop folded in at seg); also resets out/g_total
__global__ __launch_bounds__(256) void count_kernel(const int* __restrict__ ei,
                                                    float* __restrict__ out) {
    if (blockIdx.x == 0) {
        if (threadIdx.x < BB) out[threadIdx.x] = 0.0f;
        if (threadIdx.x == BB) g_total = 0;
    }
    int e4 = blockIdx.x * 256 + threadIdx.x;
    if (e4 < EE / 4) {
        int4 d = ((const int4*)(ei + EE))[e4];
        atomicAdd(&g_degi[d.x], 1);
        atomicAdd(&g_degi[d.y], 1);
        atomicAdd(&g_degi[d.z], 1);
        atomicAdd(&g_degi[d.w], 1);
    }
}

// parallel segment assignment (order-free CSR): warp-aggregated atomic
__global__ __launch_bounds__(256) void seg_kernel() {
    int i = blockIdx.x * 256 + threadIdx.x;
    int lane = threadIdx.x & 31;
    int m = 0;
    if (i < NN) { m = g_degi[i]; g_degi[i] = 0; }   // m = edge count; reset for next call
    int incl = m;
    #pragma unroll
    for (int o = 1; o < 32; o <<= 1) {
        int v = __shfl_up_sync(FULLM, incl, o);
        if (lane >= o) incl += v;
    }
    int base = 0;
    if (lane == 31) base = atomicAdd(&g_total, incl);
    base = __shfl_sync(FULLM, base, 31);
    if (i < NN) {
        int start = base + incl - m;
        g_rowstart[i] = start;
        g_rowend[i]   = start + m;
        g_cursor[i]   = start;
        g_dinv[i]     = rsqrtf((float)(m + 1));     // +1 = self-loop
    }
}

// ---------------- fp8 helpers ------------------------------------------------
__device__ __forceinline__ float fp82f(unsigned char b) {
    return __half2float(__half(__nv_cvt_fp8_to_halfraw((__nv_fp8_storage_t)b, __NV_E4M3)));
}

// ---------------- dense F x F matmul (warp per row); mm1 also does CSR fill --
__global__ __launch_bounds__(256) void mm_kernel(const float* __restrict__ x,
                                                 const float* __restrict__ W,
                                                 int from_x,
                                                 const int* __restrict__ ei) {
    int t = threadIdx.x, lane = t & 31, w = t >> 5;

    // fused CSR fill (layer-1 launch only): low blocks scatter edge sources
    if (from_x) {
        int e4 = blockIdx.x * 256 + t;
        if (e4 < EE / 4) {
            int4 s = ((const int4*)ei)[e4];
            int4 d = ((const int4*)(ei + EE))[e4];
            g_csrc[atomicAdd(&g_cursor[d.x], 1)] = s.x;
            g_csrc[atomicAdd(&g_cursor[d.y], 1)] = s.y;
            g_csrc[atomicAdd(&g_cursor[d.z], 1)] = s.z;
            g_csrc[atomicAdd(&g_cursor[d.w], 1)] = s.w;
        }
    }

    float wc[32];
    #pragma unroll
    for (int k = 0; k < 32; ++k) wc[k] = W[k * 32 + lane];

    unsigned char* outB = (unsigned char*)g_bufA8;
    const unsigned char* inB = (const unsigned char*)g_bufB8;

    int nwarps = gridDim.x * 8;
    for (int row = blockIdx.x * 8 + w; row < NB; row += nwarps) {
        int n = row >> 3;
        float xv;
        if (from_x) xv = x[((size_t)(row & 7) * NN + n) * 32 + lane];
        else        xv = fp82f(inB[(size_t)row * 32 + lane]);
        float a0 = 0.f, a1 = 0.f;
        #pragma unroll
        for (int k = 0; k < 32; k += 2) {
            a0 = fmaf(__shfl_sync(FULLM, xv, k),     wc[k],     a0);
            a1 = fmaf(__shfl_sync(FULLM, xv, k + 1), wc[k + 1], a1);
        }
        outB[(size_t)row * 32 + lane] =
            (unsigned char)__nv_cvt_float_to_fp8((a0 + a1) * g_dinv[n],
                                                 __NV_SATFINITE, __NV_E4M3);
    }
}

// ---------------- gather helpers ---------------------------------------------
// accumulate one uint4 (16 fp8 = 8 fp8x2) into 8 half2 accumulators
__device__ __forceinline__ void accv(__half2 (&acc)[8], uint4 v) {
    const __nv_fp8x2_storage_t* p = (const __nv_fp8x2_storage_t*)&v;
    #pragma unroll
    for (int i = 0; i < 8; ++i)
        acc[i] = __hadd2(acc[i], __half2(__nv_cvt_fp8x2_to_halfraw2(p[i], __NV_E4M3)));
}

// half-warp (16 lanes) per node: lane c owns bytes [16c,16c+16) of the 256B row
__device__ __forceinline__ void gather_body(__half2 (&acc)[8], int n, int c) {
    const uint4* __restrict__ gin = g_bufA8;
    const int* __restrict__ csrc = g_csrc;
    #pragma unroll
    for (int i = 0; i < 8; ++i) acc[i] = __half2(__float2half(0.f), __float2half(0.f));
    accv(acc, gin[n * 16 + c]);                             // self term
    int j = g_rowstart[n], jend = g_rowend[n];
    if (j + 4 <= jend) {
        int s0 = __ldg(csrc + j), s1 = __ldg(csrc + j + 1);
        int s2 = __ldg(csrc + j + 2), s3 = __ldg(csrc + j + 3);
        j += 4;
        while (j + 4 <= jend) {
            uint4 v0 = gin[s0 * 16 + c];
            uint4 v1 = gin[s1 * 16 + c];
            uint4 v2 = gin[s2 * 16 + c];
            uint4 v3 = gin[s3 * 16 + c];
            s0 = __ldg(csrc + j);     s1 = __ldg(csrc + j + 1);
            s2 = __ldg(csrc + j + 2); s3 = __ldg(csrc + j + 3);
            j += 4;
            accv(acc, v0); accv(acc, v1); accv(acc, v2); accv(acc, v3);
        }
        uint4 v0 = gin[s0 * 16 + c];
        uint4 v1 = gin[s1 * 16 + c];
        uint4 v2 = gin[s2 * 16 + c];
        uint4 v3 = gin[s3 * 16 + c];
        accv(acc, v0); accv(acc, v1); accv(acc, v2); accv(acc, v3);
    }
    for (; j < jend; ++j) accv(acc, gin[__ldg(csrc + j) * 16 + c]);
}

// gather + bias + relu -> bufB8 (fp8). block = 8 warps = 16 nodes.
__global__ __launch_bounds__(256) void gather1_kernel(const float* __restrict__ bias) {
    int t = threadIdx.x, lane = t & 31;
    int c = lane & 15;
    int n = blockIdx.x * 16 + ((t >> 5) << 1) + (lane >> 4);
    __half2 acc[8];
    gather_body(acc, n, c);
    float dn = g_dinv[n];
    int f0 = (c & 1) * 16;                                  // feature base within row
    union { unsigned short h[8]; uint4 v; } r;
    #pragma unroll
    for (int i = 0; i < 8; ++i) {
        float2 f = __half22float2(acc[i]);
        float lo = fmaxf(fmaf(dn, f.x, bias[f0 + 2 * i]),     0.f);
        float hi = fmaxf(fmaf(dn, f.y, bias[f0 + 2 * i + 1]), 0.f);
        r.h[i] = (unsigned short)__nv_cvt_float2_to_fp8x2(make_float2(lo, hi),
                                                          __NV_SATFINITE, __NV_E4M3);
    }
    g_bufB8[n * 16 + c] = r.v;
}

// gather + bias + relu, fused layer-3 linear (dot with W3) -> g_h3
__global__ __launch_bounds__(256) void gather2_kernel(const float* __restrict__ bias,
                                                      const float* __restrict__ W3) {
    int t = threadIdx.x, lane = t & 31;
    int c = lane & 15;
    int n = blockIdx.x * 16 + ((t >> 5) << 1) + (lane >> 4);
    __half2 acc[8];
    gather_body(acc, n, c);
    float dn = g_dinv[n];
    int f0 = (c & 1) * 16;
    float s = 0.f;
    #pragma unroll
    for (int i = 0; i < 8; ++i) {
        float2 f = __half22float2(acc[i]);
        float lo = fmaxf(fmaf(dn, f.x, bias[f0 + 2 * i]),     0.f);
        float hi = fmaxf(fmaf(dn, f.y, bias[f0 + 2 * i + 1]), 0.f);
        s = fmaf(lo, W3[f0 + 2 * i], s);
        s = fmaf(hi, W3[f0 + 2 * i + 1], s);
    }
    s += __shfl_xor_sync(FULLM, s, 1);                      // merge the 2 feature halves
    if ((c & 1) == 0) g_h3[n * 8 + (c >> 1)] = dn * s;      // b = c>>1
}

// ---------------- final: aggregate F=1, sigmoid, per-batch sum ---------------
// 2 lanes per node; each lane loads float4 (4 batch slots)
__global__ __launch_bounds__(256) void final_kernel(const float* __restrict__ b3,
                                                    float* __restrict__ out) {
    int t = threadIdx.x, lane = t & 31, wid = t >> 5;
    int node = blockIdx.x * 128 + (t >> 1);
    int h = t & 1;
    const float4* __restrict__ h3v = (const float4*)g_h3;
    float4 p = make_float4(0.f, 0.f, 0.f, 0.f);
    if (node < NN) {
        float4 acc = h3v[node * 2 + h];
        int jb = g_rowstart[node], je = g_rowend[node];
        for (int j = jb; j < je; ++j) {
            float4 v = h3v[g_csrc[j] * 2 + h];
            acc.x += v.x; acc.y += v.y; acc.z += v.z; acc.w += v.w;
        }
        float dn = g_dinv[node], bb = b3[0];
        p.x = 1.f / (1.f + expf(-fmaf(dn, acc.x, bb)));
        p.y = 1.f / (1.f + expf(-fmaf(dn, acc.y, bb)));
        p.z = 1.f / (1.f + expf(-fmaf(dn, acc.z, bb)));
        p.w = 1.f / (1.f + expf(-fmaf(dn, acc.w, bb)));
    }
    // reduce over same-h lanes within warp (xor 2,4,8,16)
    #pragma unroll
    for (int o = 2; o <= 16; o <<= 1) {
        p.x += __shfl_xor_sync(FULLM, p.x, o);
        p.y += __shfl_xor_sync(FULLM, p.y, o);
        p.z += __shfl_xor_sync(FULLM, p.z, o);
        p.w += __shfl_xor_sync(FULLM, p.w, o);
    }
    __shared__ float4 sred[16];
    if (lane < 2) sred[wid * 2 + lane] = p;
    __syncthreads();
    if (t < 16) {
        float4 v = sred[t];
        #pragma unroll
        for (int o = 2; o <= 8; o <<= 1) {                  // reduce across 8 warps
            v.x += __shfl_xor_sync(0x0000ffffu, v.x, o);
            v.y += __shfl_xor_sync(0x0000ffffu, v.y, o);
            v.z += __shfl_xor_sync(0x0000ffffu, v.z, o);
            v.w += __shfl_xor_sync(0x0000ffffu, v.w, o);
        }
        if (t < 2) {
            atomicAdd(&out[t * 4 + 0], v.x);
            atomicAdd(&out[t * 4 + 1], v.y);
            atomicAdd(&out[t * 4 + 2], v.z);
            atomicAdd(&out[t * 4 + 3], v.w);
        }
    }
}

// ---------------- launch -----------------------------------------------------
extern "C" void kernel_launch(void* const* d_in, const int* in_sizes, int n_in,
                              void* d_out, int out_size) {
    const float* x  = (const float*)d_in[0];
    const float* W1 = (const float*)d_in[1];
    const float* b1 = (const float*)d_in[2];
    const float* W2 = (const float*)d_in[3];
    const float* b2 = (const float*)d_in[4];
    const float* W3 = (const float*)d_in[5];
    const float* b3 = (const float*)d_in[6];
    const int*   ei = (const int*)d_in[7];
    float* out = (float*)d_out;

    count_kernel<<<(EE / 4 + 255) / 256, 256>>>(ei, out);
    seg_kernel<<<(NN + 255) / 256, 256>>>();
    mm_kernel<<<1184, 256>>>(x, W1, 1, ei);     // x @ W1 (+ fused CSR fill) -> bufA8
    gather1_kernel<<<NN / 16, 256>>>(b1);       // aggregate + relu -> bufB8
    mm_kernel<<<1184, 256>>>(x, W2, 0, ei);     // bufB8 @ W2 -> bufA8
    gather2_kernel<<<NN / 16, 256>>>(b2, W3);   // aggregate + relu + @W3 -> g_h3
    final_kernel<<<(NN + 127) / 128, 256>>>(b3, out);
}

// round 8
// speedup vs baseline: 2.7806x; 1.6326x over previous
#include <cuda_runtime.h>
#include <cuda_fp16.h>
#include <cuda_fp8.h>
#include <math.h>

#define NN 50000
#define BB 8
#define FF 32
#define EE 800000
#define NB (NN * BB)          // 400000 (n,b) rows
#define FULLM 0xffffffffu

// node row = 256 fp8 = 256 B = 16 uint4, layout [n][b][f]
__device__ uint4  g_bufA8[NN * 16];    // 12.8 MB  (dinv-prescaled x, fp8 e4m3)
__device__ uint4  g_bufB8[NN * 16];    // 12.8 MB  (dinv-prescaled h1, fp8 e4m3)
__device__ float  g_h3[NN * BB];       // 1.6 MB   (dinv-prescaled h2@W3, [n][b])
__device__ int    g_degi[NN];          // zero-init; reset to 0 by seg each call
__device__ float  g_dinv[NN];
__device__ int    g_rowstart[NN];
__device__ int    g_rowend[NN];
__device__ int    g_cursor[NN];
__device__ int    g_csrc[EE];
__device__ int    g_total;             // reset to 0 by count each call

// ---------------- CSR build --------------------------------------------------
__global__ __launch_bounds__(256) void count_kernel(const int* __restrict__ ei,
                                                    float* __restrict__ out) {
    if (blockIdx.x == 0) {
        if (threadIdx.x < BB) out[threadIdx.x] = 0.0f;
        if (threadIdx.x == BB) g_total = 0;
    }
    int e4 = blockIdx.x * 256 + threadIdx.x;
    if (e4 < EE / 4) {
        int4 d = ((const int4*)(ei + EE))[e4];
        atomicAdd(&g_degi[d.x], 1);
        atomicAdd(&g_degi[d.y], 1);
        atomicAdd(&g_degi[d.z], 1);
        atomicAdd(&g_degi[d.w], 1);
    }
}

__global__ __launch_bounds__(256) void seg_kernel() {
    int i = blockIdx.x * 256 + threadIdx.x;
    int lane = threadIdx.x & 31;
    int m = 0;
    if (i < NN) { m = g_degi[i]; g_degi[i] = 0; }   // edge count; reset for next call
    int incl = m;
    #pragma unroll
    for (int o = 1; o < 32; o <<= 1) {
        int v = __shfl_up_sync(FULLM, incl, o);
        if (lane >= o) incl += v;
    }
    int base = 0;
    if (lane == 31) base = atomicAdd(&g_total, incl);
    base = __shfl_sync(FULLM, base, 31);
    if (i < NN) {
        int start = base + incl - m;
        g_rowstart[i] = start;
        g_rowend[i]   = start + m;
        g_cursor[i]   = start;
        g_dinv[i]     = rsqrtf((float)(m + 1));     // +1 = self-loop
    }
}

// ---------------- prep: x -> fp8(dinv*x), layout [n][b][f]; fused CSR fill ---
__global__ __launch_bounds__(256) void prep_kernel(const float* __restrict__ x,
                                                   const int* __restrict__ ei) {
    int gid = blockIdx.x * 256 + threadIdx.x;

    if (gid < EE / 4) {                             // CSR fill (first 782 blocks)
        int4 s = ((const int4*)ei)[gid];
        int4 d = ((const int4*)(ei + EE))[gid];
        g_csrc[atomicAdd(&g_cursor[d.x], 1)] = s.x;
        g_csrc[atomicAdd(&g_cursor[d.y], 1)] = s.y;
        g_csrc[atomicAdd(&g_cursor[d.z], 1)] = s.z;
        g_csrc[atomicAdd(&g_cursor[d.w], 1)] = s.w;
    }

    // prescale + quantize: thread handles 8 features of one (n,b) row
    int row = gid >> 2;                             // n*8 + b
    int part = gid & 3;
    int n = row >> 3, b = row & 7;
    const float4* xs = (const float4*)(x + ((size_t)b * NN + n) * 32 + part * 8);
    float4 v0 = xs[0], v1 = xs[1];
    float dn = g_dinv[n];
    union { unsigned short h[4]; uint2 v; } r;
    r.h[0] = (unsigned short)__nv_cvt_float2_to_fp8x2(make_float2(v0.x * dn, v0.y * dn), __NV_SATFINITE, __NV_E4M3);
    r.h[1] = (unsigned short)__nv_cvt_float2_to_fp8x2(make_float2(v0.z * dn, v0.w * dn), __NV_SATFINITE, __NV_E4M3);
    r.h[2] = (unsigned short)__nv_cvt_float2_to_fp8x2(make_float2(v1.x * dn, v1.y * dn), __NV_SATFINITE, __NV_E4M3);
    r.h[3] = (unsigned short)__nv_cvt_float2_to_fp8x2(make_float2(v1.z * dn, v1.w * dn), __NV_SATFINITE, __NV_E4M3);
    ((uint2*)g_bufA8)[gid] = r.v;
}

// ---------------- gather + in-register matmul --------------------------------
__device__ __forceinline__ void accv(__half2 (&acc)[8], uint4 v) {
    const __nv_fp8x2_storage_t* p = (const __nv_fp8x2_storage_t*)&v;
    #pragma unroll
    for (int i = 0; i < 8; ++i)
        acc[i] = __hadd2(acc[i], __half2(__nv_cvt_fp8x2_to_halfraw2(p[i], __NV_E4M3)));
}

// half-warp per node: lane c owns bytes [16c,16c+16) of the 256B row
__device__ __forceinline__ void gather_body(__half2 (&acc)[8], const uint4* __restrict__ gin,
                                            int n, int c) {
    const int* __restrict__ csrc = g_csrc;
    #pragma unroll
    for (int i = 0; i < 8; ++i) acc[i] = __floats2half2_rn(0.f, 0.f);
    accv(acc, gin[n * 16 + c]);                             // self term
    int j = g_rowstart[n], jend = g_rowend[n];
    if (j + 4 <= jend) {
        int s0 = __ldg(csrc + j), s1 = __ldg(csrc + j + 1);
        int s2 = __ldg(csrc + j + 2), s3 = __ldg(csrc + j + 3);
        j += 4;
        while (j + 4 <= jend) {
            uint4 v0 = gin[s0 * 16 + c];
            uint4 v1 = gin[s1 * 16 + c];
            uint4 v2 = gin[s2 * 16 + c];
            uint4 v3 = gin[s3 * 16 + c];
            s0 = __ldg(csrc + j);     s1 = __ldg(csrc + j + 1);
            s2 = __ldg(csrc + j + 2); s3 = __ldg(csrc + j + 3);
            j += 4;
            accv(acc, v0); accv(acc, v1); accv(acc, v2); accv(acc, v3);
        }
        uint4 v0 = gin[s0 * 16 + c];
        uint4 v1 = gin[s1 * 16 + c];
        uint4 v2 = gin[s2 * 16 + c];
        uint4 v3 = gin[s3 * 16 + c];
        accv(acc, v0); accv(acc, v1); accv(acc, v2); accv(acc, v3);
    }
    for (; j < jend; ++j) accv(acc, gin[__ldg(csrc + j) * 16 + c]);
}

// agg -> y = dn*acc -> out = y @ W (half2 accum).  out covers f' in [(c&1)*16, +16)
__device__ __forceinline__ void agg_mm(__half2 (&out)[8], const uint4* __restrict__ gin,
                                       const __half2 (*sW)[16], int n, int c, float dn) {
    __half2 y[8];
    gather_body(y, gin, n, c);
    __half2 hdn = __floats2half2_rn(dn, dn);
    #pragma unroll
    for (int i = 0; i < 8; ++i) y[i] = __hmul2(y[i], hdn);
    __half2 o[8];
    #pragma unroll
    for (int i = 0; i < 8; ++i) o[i] = __shfl_xor_sync(FULLM, y[i], 1);
    int hi = c & 1;
    __half2 yfull[16];                                      // k-pairs 0..15
    #pragma unroll
    for (int i = 0; i < 8; ++i) {
        yfull[i]     = hi ? o[i] : y[i];
        yfull[8 + i] = hi ? y[i] : o[i];
    }
    #pragma unroll
    for (int i = 0; i < 8; ++i) out[i] = __floats2half2_rn(0.f, 0.f);
    int pbase = hi ? 8 : 0;
    #pragma unroll
    for (int kp = 0; kp < 16; ++kp) {
        __half2 yk = yfull[kp];
        __half2 xlo = __half2half2(__low2half(yk));
        __half2 xhi = __half2half2(__high2half(yk));
        #pragma unroll
        for (int i = 0; i < 8; ++i) {
            out[i] = __hfma2(xlo, sW[2 * kp][pbase + i], out[i]);
            out[i] = __hfma2(xhi, sW[2 * kp + 1][pbase + i], out[i]);
        }
    }
}

// layer 1: agg(x8) @ W1 + b1, relu, prescale dn -> bufB8
__global__ __launch_bounds__(256) void g1_kernel(const float* __restrict__ W,
                                                 const float* __restrict__ bias) {
    __shared__ __half2 sW[32][16];
    __shared__ float sB[32];
    int t = threadIdx.x;
    for (int i = t; i < 512; i += 256) {
        int k = i >> 4, p = i & 15;
        sW[k][p] = __floats2half2_rn(W[k * 32 + 2 * p], W[k * 32 + 2 * p + 1]);
    }
    if (t < 32) sB[t] = bias[t];
    __syncthreads();

    int lane = t & 31;
    int c = lane & 15;
    int n = blockIdx.x * 16 + ((t >> 5) << 1) + (lane >> 4);
    float dn = g_dinv[n];
    __half2 out[8];
    agg_mm(out, g_bufA8, sW, n, c, dn);

    int f0 = (c & 1) * 16;
    union { unsigned short h[8]; uint4 v; } r;
    #pragma unroll
    for (int i = 0; i < 8; ++i) {
        float2 f = __half22float2(out[i]);
        float lo = fmaxf(f.x + sB[f0 + 2 * i],     0.f) * dn;
        float hv = fmaxf(f.y + sB[f0 + 2 * i + 1], 0.f) * dn;
        r.h[i] = (unsigned short)__nv_cvt_float2_to_fp8x2(make_float2(lo, hv),
                                                          __NV_SATFINITE, __NV_E4M3);
    }
    g_bufB8[n * 16 + c] = r.v;
}

// layer 2+3a: agg(h1) @ W2 + b2, relu, @W3, prescale dn -> g_h3
__global__ __launch_bounds__(256) void g2_kernel(const float* __restrict__ W,
                                                 const float* __restrict__ bias,
                                                 const float* __restrict__ W3) {
    __shared__ __half2 sW[32][16];
    __shared__ float sB[32];
    __shared__ float sW3[32];
    int t = threadIdx.x;
    for (int i = t; i < 512; i += 256) {
        int k = i >> 4, p = i & 15;
        sW[k][p] = __floats2half2_rn(W[k * 32 + 2 * p], W[k * 32 + 2 * p + 1]);
    }
    if (t < 32) { sB[t] = bias[t]; sW3[t] = W3[t]; }
    __syncthreads();

    int lane = t & 31;
    int c = lane & 15;
    int n = blockIdx.x * 16 + ((t >> 5) << 1) + (lane >> 4);
    float dn = g_dinv[n];
    __half2 out[8];
    agg_mm(out, g_bufB8, sW, n, c, dn);

    int f0 = (c & 1) * 16;
    float s = 0.f;
    #pragma unroll
    for (int i = 0; i < 8; ++i) {
        float2 f = __half22float2(out[i]);
        float lo = fmaxf(f.x + sB[f0 + 2 * i],     0.f);
        float hv = fmaxf(f.y + sB[f0 + 2 * i + 1], 0.f);
        s = fmaf(lo, sW3[f0 + 2 * i],     s);
        s = fmaf(hv, sW3[f0 + 2 * i + 1], s);
    }
    s += __shfl_xor_sync(FULLM, s, 1);                      // merge 2 feature halves
    if ((c & 1) == 0) g_h3[n * 8 + (c >> 1)] = dn * s;
}

// ---------------- final: aggregate F=1, sigmoid, per-batch sum ---------------
__global__ __launch_bounds__(256) void final_kernel(const float* __restrict__ b3,
                                                    float* __restrict__ out) {
    int t = threadIdx.x, lane = t & 31, wid = t >> 5;
    int node = blockIdx.x * 128 + (t >> 1);
    int h = t & 1;
    const float4* __restrict__ h3v = (const float4*)g_h3;
    float4 p = make_float4(0.f, 0.f, 0.f, 0.f);
    if (node < NN) {
        float4 acc = h3v[node * 2 + h];
        int jb = g_rowstart[node], je = g_rowend[node];
        for (int j = jb; j < je; ++j) {
            float4 v = h3v[g_csrc[j] * 2 + h];
            acc.x += v.x; acc.y += v.y; acc.z += v.z; acc.w += v.w;
        }
        float dn = g_dinv[node], bb = b3[0];
        p.x = 1.f / (1.f + expf(-fmaf(dn, acc.x, bb)));
        p.y = 1.f / (1.f + expf(-fmaf(dn, acc.y, bb)));
        p.z = 1.f / (1.f + expf(-fmaf(dn, acc.z, bb)));
        p.w = 1.f / (1.f + expf(-fmaf(dn, acc.w, bb)));
    }
    #pragma unroll
    for (int o = 2; o <= 16; o <<= 1) {
        p.x += __shfl_xor_sync(FULLM, p.x, o);
        p.y += __shfl_xor_sync(FULLM, p.y, o);
        p.z += __shfl_xor_sync(FULLM, p.z, o);
        p.w += __shfl_xor_sync(FULLM, p.w, o);
    }
    __shared__ float4 sred[16];
    if (lane < 2) sred[wid * 2 + lane] = p;
    __syncthreads();
    if (t < 16) {
        float4 v = sred[t];
        #pragma unroll
        for (int o = 2; o <= 8; o <<= 1) {
            v.x += __shfl_xor_sync(0x0000ffffu, v.x, o);
            v.y += __shfl_xor_sync(0x0000ffffu, v.y, o);
            v.z += __shfl_xor_sync(0x0000ffffu, v.z, o);
            v.w += __shfl_xor_sync(0x0000ffffu, v.w, o);
        }
        if (t < 2) {
            atomicAdd(&out[t * 4 + 0], v.x);
            atomicAdd(&out[t * 4 + 1], v.y);
            atomicAdd(&out[t * 4 + 2], v.z);
            atomicAdd(&out[t * 4 + 3], v.w);
        }
    }
}

// ---------------- launch -----------------------------------------------------
extern "C" void kernel_launch(void* const* d_in, const int* in_sizes, int n_in,
                              void* d_out, int out_size) {
    const float* x  = (const float*)d_in[0];
    const float* W1 = (const float*)d_in[1];
    const float* b1 = (const float*)d_in[2];
    const float* W2 = (const float*)d_in[3];
    const float* b2 = (const float*)d_in[4];
    const float* W3 = (const float*)d_in[5];
    const float* b3 = (const float*)d_in[6];
    const int*   ei = (const int*)d_in[7];
    float* out = (float*)d_out;

    count_kernel<<<(EE / 4 + 255) / 256, 256>>>(ei, out);
    seg_kernel<<<(NN + 255) / 256, 256>>>();
    prep_kernel<<<NB * 4 / 256, 256>>>(x, ei);    // prescale x -> bufA8 (+ CSR fill)
    g1_kernel<<<NN / 16, 256>>>(W1, b1);          // agg + @W1 + relu -> bufB8
    g2_kernel<<<NN / 16, 256>>>(W2, b2, W3);      // agg + @W2 + relu + @W3 -> g_h3
    final_kernel<<<(NN + 127) / 128, 256>>>(b3, out);
}

// round 13
// speedup vs baseline: 3.5055x; 1.2607x over previous
#include <cuda_runtime.h>
#include <cuda_fp16.h>
#include <cuda_fp8.h>
#include <mma.h>
#include <math.h>

#define NN 50000
#define BB 8
#define EE 800000
#define NB (NN * BB)
#define FM 0xffffffffu
#define YSTR 48
#define OSTR 40

using namespace nvcuda;

__device__ uint4 g_bufA8[NN * 16];
__device__ uint4 g_bufB8[NN * 16];
__device__ float g_h3[NN * BB];
__device__ int   g_degi[NN];
__device__ float g_dinv[NN];
__device__ int   g_rs[NN];
__device__ int   g_re[NN];
__device__ int   g_cur[NN];
__device__ int   g_csrc[EE];
__device__ int   g_total;

__device__ __forceinline__ unsigned short q2(float a, float b) {
    return (unsigned short)__nv_cvt_float2_to_fp8x2(make_float2(a, b), __NV_SATFINITE, __NV_E4M3);
}

__global__ __launch_bounds__(256) void count_kernel(const int* __restrict__ ei, float* __restrict__ out) {
    if (blockIdx.x == 0) {
        if (threadIdx.x < BB) out[threadIdx.x] = 0.0f;
        if (threadIdx.x == BB) g_total = 0;
    }
    int e4 = blockIdx.x * 256 + threadIdx.x;
    if (e4 < EE / 4) {
        int4 d = ((const int4*)(ei + EE))[e4];
        atomicAdd(&g_degi[d.x], 1);
        atomicAdd(&g_degi[d.y], 1);
        atomicAdd(&g_degi[d.z], 1);
        atomicAdd(&g_degi[d.w], 1);
    }
}

__global__ __launch_bounds__(256) void seg_kernel() {
    int i = blockIdx.x * 256 + threadIdx.x;
    int lane = threadIdx.x & 31;
    int m = 0;
    if (i < NN) { m = g_degi[i]; g_degi[i] = 0; }
    int incl = m;
    for (int o = 1; o < 32; o <<= 1) {
        int v = __shfl_up_sync(FM, incl, o);
        if (lane >= o) incl += v;
    }
    int base = 0;
    if (lane == 31) base = atomicAdd(&g_total, incl);
    base = __shfl_sync(FM, base, 31);
    if (i < NN) {
        int st = base + incl - m;
        g_rs[i] = st;
        g_re[i] = st + m;
        g_cur[i] = st;
        g_dinv[i] = rsqrtf((float)(m + 1));
    }
}

__global__ __launch_bounds__(256) void prep_kernel(const float* __restrict__ x, const int* __restrict__ ei) {
    int gid = blockIdx.x * 256 + threadIdx.x;
    if (gid < EE / 4) {
        int4 s = ((const int4*)ei)[gid];
        int4 d = ((const int4*)(ei + EE))[gid];
        g_csrc[atomicAdd(&g_cur[d.x], 1)] = s.x;
        g_csrc[atomicAdd(&g_cur[d.y], 1)] = s.y;
        g_csrc[atomicAdd(&g_cur[d.z], 1)] = s.z;
        g_csrc[atomicAdd(&g_cur[d.w], 1)] = s.w;
    }
    int row = gid >> 2, part = gid & 3;
    int n = row >> 3, b = row & 7;
    const float4* xs = (const float4*)(x + ((size_t)b * NN + n) * 32 + part * 8);
    float4 v0 = xs[0], v1 = xs[1];
    float dn = g_dinv[n];
    union { unsigned short h[4]; uint2 v; } r;
    r.h[0] = q2(v0.x * dn, v0.y * dn);
    r.h[1] = q2(v0.z * dn, v0.w * dn);
    r.h[2] = q2(v1.x * dn, v1.y * dn);
    r.h[3] = q2(v1.z * dn, v1.w * dn);
    ((uint2*)g_bufA8)[gid] = r.v;
}

__device__ __forceinline__ void accv(__half2* acc, uint4 v) {
    const __nv_fp8x2_storage_t* p = (const __nv_fp8x2_storage_t*)&v;
    #pragma unroll
    for (int i = 0; i < 8; ++i)
        acc[i] = __hadd2(acc[i], __half2(__nv_cvt_fp8x2_to_halfraw2(p[i], __NV_E4M3)));
}

__device__ __forceinline__ void gather_body(__half2* acc, const uint4* __restrict__ gin, int n, int c) {
    const int* __restrict__ cs = g_csrc;
    #pragma unroll
    for (int i = 0; i < 8; ++i) acc[i] = __floats2half2_rn(0.f, 0.f);
    accv(acc, gin[n * 16 + c]);
    int j = g_rs[n], je = g_re[n];
    if (j + 4 <= je) {
        int s0 = __ldg(cs + j), s1 = __ldg(cs + j + 1), s2 = __ldg(cs + j + 2), s3 = __ldg(cs + j + 3);
        j += 4;
        while (j + 4 <= je) {
            uint4 v0 = gin[s0 * 16 + c], v1 = gin[s1 * 16 + c], v2 = gin[s2 * 16 + c], v3 = gin[s3 * 16 + c];
            s0 = __ldg(cs + j); s1 = __ldg(cs + j + 1); s2 = __ldg(cs + j + 2); s3 = __ldg(cs + j + 3);
            j += 4;
            accv(acc, v0); accv(acc, v1); accv(acc, v2); accv(acc, v3);
        }
        uint4 v0 = gin[s0 * 16 + c], v1 = gin[s1 * 16 + c], v2 = gin[s2 * 16 + c], v3 = gin[s3 * 16 + c];
        accv(acc, v0); accv(acc, v1); accv(acc, v2); accv(acc, v3);
    }
    for (; j < je; ++j) accv(acc, gin[__ldg(cs + j) * 16 + c]);
}

// gather 16 nodes into smem Y, then per-warp wmma: O[128x32] = Y[128x32] @ W[32x32]
__device__ __forceinline__ void gather_wmma(float* sO, __half* sY, const __half* sW,
                                            const uint4* __restrict__ gin, int n0, int t) {
    int lane = t & 31, w = t >> 5, c = lane & 15;
    int nl = 2 * w + (lane >> 4);
    __half2 acc[8];
    gather_body(acc, gin, n0 + nl, c);
    int r = nl * 8 + (c >> 1);
    int f0 = (c & 1) * 16;
    *(uint4*)&sY[r * YSTR + f0] = *(uint4*)&acc[0];
    *(uint4*)&sY[r * YSTR + f0 + 8] = *(uint4*)&acc[4];
    __syncwarp();

    wmma::fragment<wmma::accumulator, 16, 16, 16, float> d0, d1;
    wmma::fill_fragment(d0, 0.f);
    wmma::fill_fragment(d1, 0.f);
    #pragma unroll
    for (int kt = 0; kt < 2; ++kt) {
        wmma::fragment<wmma::matrix_a, 16, 16, 16, __half, wmma::row_major> af;
        wmma::load_matrix_sync(af, &sY[w * 16 * YSTR + kt * 16], YSTR);
        wmma::fragment<wmma::matrix_b, 16, 16, 16, __half, wmma::row_major> bf;
        wmma::load_matrix_sync(bf, &sW[kt * 16 * YSTR], YSTR);
        wmma::mma_sync(d0, af, bf, d0);
        wmma::load_matrix_sync(bf, &sW[kt * 16 * YSTR + 16], YSTR);
        wmma::mma_sync(d1, af, bf, d1);
    }
    wmma::store_matrix_sync(&sO[w * 16 * OSTR], d0, OSTR, wmma::mem_row_major);
    wmma::store_matrix_sync(&sO[w * 16 * OSTR + 16], d1, OSTR, wmma::mem_row_major);
    __syncwarp();
}

__global__ __launch_bounds__(256) void g1_kernel(const float* __restrict__ W, const float* __restrict__ bias) {
    __shared__ __half sW[32 * YSTR];
    __shared__ __half sY[128 * YSTR];
    __shared__ float sO[128 * OSTR];
    __shared__ float sB[32];
    int t = threadIdx.x;
    int n0 = blockIdx.x * 16;
    for (int i = t; i < 1024; i += 256) sW[(i >> 5) * YSTR + (i & 31)] = __float2half(W[i]);
    if (t < 32) sB[t] = bias[t];
    __syncthreads();

    gather_wmma(sO, sY, sW, g_bufA8, n0, t);

    int r = t >> 1, hf = t & 1, f0 = hf * 16;
    int n = n0 + (r >> 3), b = r & 7;
    float dn = g_dinv[n];
    const float* o = &sO[r * OSTR + f0];
    union { unsigned short h[8]; uint4 v; } q;
    #pragma unroll
    for (int i = 0; i < 8; ++i) {
        float a = fmaxf(fmaf(dn, o[2 * i], sB[f0 + 2 * i]), 0.f) * dn;
        float bb = fmaxf(fmaf(dn, o[2 * i + 1], sB[f0 + 2 * i + 1]), 0.f) * dn;
        q.h[i] = q2(a, bb);
    }
    g_bufB8[n * 16 + b * 2 + hf] = q.v;
}

__global__ __launch_bounds__(256) void g2_kernel(const float* __restrict__ W, const float* __restrict__ bias, const float* __restrict__ W3) {
    __shared__ __half sW[32 * YSTR];
    __shared__ __half sY[128 * YSTR];
    __shared__ float sO[128 * OSTR];
    __shared__ float sB[32];
    __shared__ float sW3[32];
    int t = threadIdx.x;
    int n0 = blockIdx.x * 16;
    for (int i = t; i < 1024; i += 256) sW[(i >> 5) * YSTR + (i & 31)] = __float2half(W[i]);
    if (t < 32) { sB[t] = bias[t]; sW3[t] = W3[t]; }
    __syncthreads();

    gather_wmma(sO, sY, sW, g_bufB8, n0, t);

    int r = t >> 1, hf = t & 1, f0 = hf * 16;
    int n = n0 + (r >> 3), b = r & 7;
    float dn = g_dinv[n];
    const float* o = &sO[r * OSTR + f0];
    float s = 0.f;
    #pragma unroll
    for (int i = 0; i < 16; ++i) {
        float h = fmaxf(fmaf(dn, o[i], sB[f0 + i]), 0.f);
        s = fmaf(h, sW3[f0 + i], s);
    }
    s += __shfl_xor_sync(FM, s, 1);
    if (hf == 0) g_h3[n * 8 + b] = dn * s;
}

__global__ __launch_bounds__(256) void final_kernel(const float* __restrict__ b3, float* __restrict__ out) {
    int t = threadIdx.x, lane = t & 31, wid = t >> 5;
    int node = blockIdx.x * 128 + (t >> 1);
    int h = t & 1;
    const float4* __restrict__ h3v = (const float4*)g_h3;
    float p[4] = {0.f, 0.f, 0.f, 0.f};
    if (node < NN) {
        float4 a = h3v[node * 2 + h];
        int jb = g_rs[node], je = g_re[node];
        for (int j = jb; j < je; ++j) {
            float4 v = h3v[g_csrc[j] * 2 + h];
            a.x += v.x; a.y += v.y; a.z += v.z; a.w += v.w;
        }
        float dn = g_dinv[node], bb = b3[0];
        p[0] = 1.f / (1.f + expf(-fmaf(dn, a.x, bb)));
        p[1] = 1.f / (1.f + expf(-fmaf(dn, a.y, bb)));
        p[2] = 1.f / (1.f + expf(-fmaf(dn, a.z, bb)));
        p[3] = 1.f / (1.f + expf(-fmaf(dn, a.w, bb)));
    }
    for (int o = 2; o <= 16; o <<= 1) {
        #pragma unroll
        for (int i = 0; i < 4; ++i) p[i] += __shfl_xor_sync(FM, p[i], o);
    }
    __shared__ float sred[16][4];
    if (lane < 2) {
        #pragma unroll
        for (int i = 0; i < 4; ++i) sred[wid * 2 + lane][i] = p[i];
    }
    __syncthreads();
    if (t < 16) {
        float v[4];
        #pragma unroll
        for (int i = 0; i < 4; ++i) v[i] = sred[t][i];
        for (int o = 2; o <= 8; o <<= 1) {
            #pragma unroll
            for (int i = 0; i < 4; ++i) v[i] += __shfl_xor_sync(0x0000ffffu, v[i], o);
        }
        if (t < 2) {
            #pragma unroll
            for (int i = 0; i < 4; ++i) atomicAdd(&out[t * 4 + i], v[i]);
        }
    }
}

extern "C" void kernel_launch(void* const* d_in, const int* in_sizes, int n_in, void* d_out, int out_size) {
    const float* x  = (const float*)d_in[0];
    const float* W1 = (const float*)d_in[1];
    const float* b1 = (const float*)d_in[2];
    const float* W2 = (const float*)d_in[3];
    const float* b2 = (const float*)d_in[4];
    const float* W3 = (const float*)d_in[5];
    const float* b3 = (const float*)d_in[6];
    const int*   ei = (const int*)d_in[7];
    float* out = (float*)d_out;

    count_kernel<<<(EE / 4 + 255) / 256, 256>>>(ei, out);
    seg_kernel<<<(NN + 255) / 256, 256>>>();
    prep_kernel<<<NB * 4 / 256, 256>>>(x, ei);
    g1_kernel<<<NN / 16, 256>>>(W1, b1);
    g2_kernel<<<NN / 16, 256>>>(W2, b2, W3);
    final_kernel<<<(NN + 127) / 128, 256>>>(b3, out);
}

// round 14
// speedup vs baseline: 3.8649x; 1.1025x over previous
#include <cuda_runtime.h>
#include <cuda_fp16.h>
#include <cuda_fp8.h>
#include <mma.h>
#include <math.h>

#define NN 50000
#define BB 8
#define EE 800000
#define NB (NN * BB)
#define FM 0xffffffffu
#define YSTR 48

using namespace nvcuda;

__device__ uint4 g_bufA8[NN * 16];
__device__ uint4 g_bufB8[NN * 16];
__device__ float g_h3[NN * BB];
__device__ int   g_degi[NN];
__device__ float g_dinv[NN];
__device__ int   g_rs[NN];
__device__ int   g_re[NN];
__device__ int   g_cur[NN];
__device__ int   g_csrc[EE];
__device__ int   g_total;

__device__ __forceinline__ unsigned short q2(float a, float b) {
    return (unsigned short)__nv_cvt_float2_to_fp8x2(make_float2(a, b), __NV_SATFINITE, __NV_E4M3);
}

__global__ __launch_bounds__(256) void count_kernel(const int* __restrict__ ei, float* __restrict__ out) {
    if (blockIdx.x == 0) {
        if (threadIdx.x < BB) out[threadIdx.x] = 0.0f;
        if (threadIdx.x == BB) g_total = 0;
    }
    int e4 = blockIdx.x * 256 + threadIdx.x;
    if (e4 < EE / 4) {
        int4 d = ((const int4*)(ei + EE))[e4];
        atomicAdd(&g_degi[d.x], 1);
        atomicAdd(&g_degi[d.y], 1);
        atomicAdd(&g_degi[d.z], 1);
        atomicAdd(&g_degi[d.w], 1);
    }
}

__global__ __launch_bounds__(256) void seg_kernel() {
    int i = blockIdx.x * 256 + threadIdx.x;
    int lane = threadIdx.x & 31;
    int m = 0;
    if (i < NN) { m = g_degi[i]; g_degi[i] = 0; }
    int incl = m;
    for (int o = 1; o < 32; o <<= 1) {
        int v = __shfl_up_sync(FM, incl, o);
        if (lane >= o) incl += v;
    }
    int base = 0;
    if (lane == 31) base = atomicAdd(&g_total, incl);
    base = __shfl_sync(FM, base, 31);
    if (i < NN) {
        int st = base + incl - m;
        g_rs[i] = st;
        g_re[i] = st + m;
        g_cur[i] = st;
        g_dinv[i] = rsqrtf((float)(m + 1));
    }
}

__global__ __launch_bounds__(256) void prep_kernel(const float* __restrict__ x, const int* __restrict__ ei) {
    int gid = blockIdx.x * 256 + threadIdx.x;
    if (gid < EE / 4) {
        int4 s = ((const int4*)ei)[gid];
        int4 d = ((const int4*)(ei + EE))[gid];
        g_csrc[atomicAdd(&g_cur[d.x], 1)] = s.x;
        g_csrc[atomicAdd(&g_cur[d.y], 1)] = s.y;
        g_csrc[atomicAdd(&g_cur[d.z], 1)] = s.z;
        g_csrc[atomicAdd(&g_cur[d.w], 1)] = s.w;
    }
    int row = gid >> 2, part = gid & 3;
    int n = row >> 3, b = row & 7;
    const float4* xs = (const float4*)(x + ((size_t)b * NN + n) * 32 + part * 8);
    float4 v0 = xs[0], v1 = xs[1];
    float dn = g_dinv[n];
    union { unsigned short h[4]; uint2 v; } r;
    r.h[0] = q2(v0.x * dn, v0.y * dn);
    r.h[1] = q2(v0.z * dn, v0.w * dn);
    r.h[2] = q2(v1.x * dn, v1.y * dn);
    r.h[3] = q2(v1.z * dn, v1.w * dn);
    ((uint2*)g_bufA8)[gid] = r.v;
}

__device__ __forceinline__ void accv(__half2* acc, uint4 v) {
    const __nv_fp8x2_storage_t* p = (const __nv_fp8x2_storage_t*)&v;
    #pragma unroll
    for (int i = 0; i < 8; ++i)
        acc[i] = __hadd2(acc[i], __half2(__nv_cvt_fp8x2_to_halfraw2(p[i], __NV_E4M3)));
}

__device__ __forceinline__ void gather_body(__half2* acc, const uint4* __restrict__ gin, int n, int c) {
    const int* __restrict__ cs = g_csrc;
    #pragma unroll
    for (int i = 0; i < 8; ++i) acc[i] = __floats2half2_rn(0.f, 0.f);
    accv(acc, gin[n * 16 + c]);
    int j = g_rs[n], je = g_re[n];
    if (j + 4 <= je) {
        int s0 = __ldg(cs + j), s1 = __ldg(cs + j + 1), s2 = __ldg(cs + j + 2), s3 = __ldg(cs + j + 3);
        j += 4;
        while (j + 4 <= je) {
            uint4 v0 = gin[s0 * 16 + c], v1 = gin[s1 * 16 + c], v2 = gin[s2 * 16 + c], v3 = gin[s3 * 16 + c];
            s0 = __ldg(cs + j); s1 = __ldg(cs + j + 1); s2 = __ldg(cs + j + 2); s3 = __ldg(cs + j + 3);
            j += 4;
            accv(acc, v0); accv(acc, v1); accv(acc, v2); accv(acc, v3);
        }
        uint4 v0 = gin[s0 * 16 + c], v1 = gin[s1 * 16 + c], v2 = gin[s2 * 16 + c], v3 = gin[s3 * 16 + c];
        accv(acc, v0); accv(acc, v1); accv(acc, v2); accv(acc, v3);
    }
    for (; j < je; ++j) accv(acc, gin[__ldg(cs + j) * 16 + c]);
}

// gather 16 nodes into smem Y, per-warp wmma (f16 accum), store result back into Y in place.
// Warp w owns rows [16w, 16w+16) of sY exclusively; A-fragments are in registers before the
// store, so aliasing Y and O is safe within the warp.
__device__ __forceinline__ void gather_wmma(__half* sY, const __half* sW,
                                            const uint4* __restrict__ gin, int n0, int t) {
    int lane = t & 31, w = t >> 5, c = lane & 15;
    int nl = 2 * w + (lane >> 4);
    __half2 acc[8];
    gather_body(acc, gin, n0 + nl, c);
    int r = nl * 8 + (c >> 1);
    int f0 = (c & 1) * 16;
    *(uint4*)&sY[r * YSTR + f0] = *(uint4*)&acc[0];
    *(uint4*)&sY[r * YSTR + f0 + 8] = *(uint4*)&acc[4];
    __syncwarp();

    wmma::fragment<wmma::matrix_a, 16, 16, 16, __half, wmma::row_major> a0, a1;
    wmma::load_matrix_sync(a0, &sY[w * 16 * YSTR], YSTR);
    wmma::load_matrix_sync(a1, &sY[w * 16 * YSTR + 16], YSTR);

    wmma::fragment<wmma::accumulator, 16, 16, 16, __half> d0, d1;
    wmma::fill_fragment(d0, __float2half(0.f));
    wmma::fill_fragment(d1, __float2half(0.f));

    wmma::fragment<wmma::matrix_b, 16, 16, 16, __half, wmma::row_major> bf;
    wmma::load_matrix_sync(bf, &sW[0], YSTR);
    wmma::mma_sync(d0, a0, bf, d0);
    wmma::load_matrix_sync(bf, &sW[16], YSTR);
    wmma::mma_sync(d1, a0, bf, d1);
    wmma::load_matrix_sync(bf, &sW[16 * YSTR], YSTR);
    wmma::mma_sync(d0, a1, bf, d0);
    wmma::load_matrix_sync(bf, &sW[16 * YSTR + 16], YSTR);
    wmma::mma_sync(d1, a1, bf, d1);

    wmma::store_matrix_sync(&sY[w * 16 * YSTR], d0, YSTR, wmma::mem_row_major);
    wmma::store_matrix_sync(&sY[w * 16 * YSTR + 16], d1, YSTR, wmma::mem_row_major);
    __syncwarp();
}

__global__ __launch_bounds__(256) void g1_kernel(const float* __restrict__ W, const float* __restrict__ bias) {
    __shared__ __half sW[32 * YSTR];
    __shared__ __half sY[128 * YSTR];
    __shared__ float sB[32];
    int t = threadIdx.x;
    int n0 = blockIdx.x * 16;
    for (int i = t; i < 1024; i += 256) sW[(i >> 5) * YSTR + (i & 31)] = __float2half(W[i]);
    if (t < 32) sB[t] = bias[t];
    __syncthreads();

    gather_wmma(sY, sW, g_bufA8, n0, t);

    int r = t >> 1, hf = t & 1, f0 = hf * 16;
    int n = n0 + (r >> 3);
    float dn = g_dinv[n];
    const __half2* o = (const __half2*)&sY[r * YSTR + f0];
    union { unsigned short h[8]; uint4 v; } q;
    #pragma unroll
    for (int i = 0; i < 8; ++i) {
        float2 f = __half22float2(o[i]);
        float a = fmaxf(fmaf(dn, f.x, sB[f0 + 2 * i]), 0.f) * dn;
        float bb = fmaxf(fmaf(dn, f.y, sB[f0 + 2 * i + 1]), 0.f) * dn;
        q.h[i] = q2(a, bb);
    }
    g_bufB8[n0 * 16 + t] = q.v;
}

__global__ __launch_bounds__(256) void g2_kernel(const float* __restrict__ W, const float* __restrict__ bias, const float* __restrict__ W3) {
    __shared__ __half sW[32 * YSTR];
    __shared__ __half sY[128 * YSTR];
    __shared__ float sB[32];
    __shared__ float sW3[32];
    int t = threadIdx.x;
    int n0 = blockIdx.x * 16;
    for (int i = t; i < 1024; i += 256) sW[(i >> 5) * YSTR + (i & 31)] = __float2half(W[i]);
    if (t < 32) { sB[t] = bias[t]; sW3[t] = W3[t]; }
    __syncthreads();

    gather_wmma(sY, sW, g_bufB8, n0, t);

    int r = t >> 1, hf = t & 1, f0 = hf * 16;
    int n = n0 + (r >> 3), b = r & 7;
    float dn = g_dinv[n];
    const __half2* o = (const __half2*)&sY[r * YSTR + f0];
    float s = 0.f;
    #pragma unroll
    for (int i = 0; i < 8; ++i) {
        float2 f = __half22float2(o[i]);
        float h0 = fmaxf(fmaf(dn, f.x, sB[f0 + 2 * i]), 0.f);
        float h1 = fmaxf(fmaf(dn, f.y, sB[f0 + 2 * i + 1]), 0.f);
        s = fmaf(h0, sW3[f0 + 2 * i], s);
        s = fmaf(h1, sW3[f0 + 2 * i + 1], s);
    }
    s += __shfl_xor_sync(FM, s, 1);
    if (hf == 0) g_h3[n * 8 + b] = dn * s;
}

__global__ __launch_bounds__(256) void final_kernel(const float* __restrict__ b3, float* __restrict__ out) {
    int t = threadIdx.x, lane = t & 31, wid = t >> 5;
    int node = blockIdx.x * 128 + (t >> 1);
    int h = t & 1;
    const float4* __restrict__ h3v = (const float4*)g_h3;
    float p[4] = {0.f, 0.f, 0.f, 0.f};
    if (node < NN) {
        float4 a = h3v[node * 2 + h];
        int jb = g_rs[node], je = g_re[node];
        for (int j = jb; j < je; ++j) {
            float4 v = h3v[g_csrc[j] * 2 + h];
            a.x += v.x; a.y += v.y; a.z += v.z; a.w += v.w;
        }
        float dn = g_dinv[node], bb = b3[0];
        p[0] = 1.f / (1.f + expf(-fmaf(dn, a.x, bb)));
        p[1] = 1.f / (1.f + expf(-fmaf(dn, a.y, bb)));
        p[2] = 1.f / (1.f + expf(-fmaf(dn, a.z, bb)));
        p[3] = 1.f / (1.f + expf(-fmaf(dn, a.w, bb)));
    }
    for (int o = 2; o <= 16; o <<= 1) {
        #pragma unroll
        for (int i = 0; i < 4; ++i) p[i] += __shfl_xor_sync(FM, p[i], o);
    }
    __shared__ float sred[16][4];
    if (lane < 2) {
        #pragma unroll
        for (int i = 0; i < 4; ++i) sred[wid * 2 + lane][i] = p[i];
    }
    __syncthreads();
    if (t < 16) {
        float v[4];
        #pragma unroll
        for (int i = 0; i < 4; ++i) v[i] = sred[t][i];
        for (int o = 2; o <= 8; o <<= 1) {
            #pragma unroll
            for (int i = 0; i < 4; ++i) v[i] += __shfl_xor_sync(0x0000ffffu, v[i], o);
        }
        if (t < 2) {
            #pragma unroll
            for (int i = 0; i < 4; ++i) atomicAdd(&out[t * 4 + i], v[i]);
        }
    }
}

extern "C" void kernel_launch(void* const* d_in, const int* in_sizes, int n_in, void* d_out, int out_size) {
    const float* x  = (const float*)d_in[0];
    const float* W1 = (const float*)d_in[1];
    const float* b1 = (const float*)d_in[2];
    const float* W2 = (const float*)d_in[3];
    const float* b2 = (const float*)d_in[4];
    const float* W3 = (const float*)d_in[5];
    const float* b3 = (const float*)d_in[6];
    const int*   ei = (const int*)d_in[7];
    float* out = (float*)d_out;

    count_kernel<<<(EE / 4 + 255) / 256, 256>>>(ei, out);
    seg_kernel<<<(NN + 255) / 256, 256>>>();
    prep_kernel<<<NB * 4 / 256, 256>>>(x, ei);
    g1_kernel<<<NN / 16, 256>>>(W1, b1);
    g2_kernel<<<NN / 16, 256>>>(W2, b2, W3);
    final_kernel<<<(NN + 127) / 128, 256>>>(b3, out);
}